// round 5
// baseline (speedup 1.0000x reference)
#include <cuda_runtime.h>
#include <cstdint>
#include <cstddef>

// Problem sizes (fixed): B=128, S=2048, I=256, H=512, O=256
// Persistent-LSTM:
//  128 CTAs = 4 batch-bands(32 rows) x 32 column-CTAs(16 h-cols x 4 gates = 64 n)
//  Per-CTA SMEM weight tile [K=768][64 n] tf32, resident all 2048 steps.
//  TB=256, 8 warps, warp tile 16x16 (nt=2) -- proven R3 compute core.
//  A=[x_t | h_{t-1}] staged in 64-wide K chunks, 3-slot cp.async ring with
//  depth-2 prefetch (wait_group 1) -> L2 latency fully hidden.
//  Sync: per-producer flags g_done[cta]=t; an h-chunk load spins (warp 0 only,
//  overlapped with other warps' mma) on just the 4 producer CTAs it needs.

#define TB 256
#define NCHUNK 12
#define TOTCHUNK (2048 * NCHUNK)
#define ASLOT (32 * 68)

static __device__ float g_h[2][128 * 512];
static __device__ volatile int g_done[128];

__device__ __forceinline__ void cp16(void* dst, const void* src) {
    unsigned d = (unsigned)__cvta_generic_to_shared(dst);
    asm volatile("cp.async.cg.shared.global [%0], [%1], 16;\n" ::"r"(d), "l"(src));
}
__device__ __forceinline__ void cp_commit() { asm volatile("cp.async.commit_group;\n"); }
__device__ __forceinline__ void cp_wait1() { asm volatile("cp.async.wait_group 1;\n"); }

__device__ __forceinline__ unsigned f2tf(float x) {
    unsigned r;
    asm("cvt.rna.tf32.f32 %0, %1;" : "=r"(r) : "f"(x));
    return r;
}
__device__ __forceinline__ void mma_tf32(float c[4], unsigned a0, unsigned a1, unsigned a2,
                                         unsigned a3, unsigned b0, unsigned b1) {
    asm volatile(
        "mma.sync.aligned.m16n8k8.row.col.f32.tf32.tf32.f32 "
        "{%0,%1,%2,%3},{%4,%5,%6,%7},{%8,%9},{%0,%1,%2,%3};"
        : "+f"(c[0]), "+f"(c[1]), "+f"(c[2]), "+f"(c[3])
        : "r"(a0), "r"(a1), "r"(a2), "r"(a3), "r"(b0), "r"(b1));
}
__device__ __forceinline__ void stcg(float* p, float v) {
    asm volatile("st.global.cg.f32 [%0], %1;" ::"l"(p), "f"(v));
}

__device__ __forceinline__ float fsig(float x) { return 1.f / (1.f + __expf(-x)); }
__device__ __forceinline__ float ftanh(float x) {
    float a = fabsf(x);
    float e = __expf(2.f * a);
    float r = 1.f - 2.f / (1.f + e);
    return copysignf(r, x);
}

// SMEM (floats):
//  Ws  : 64*772  weight tile [n][k], stride 772 (conflict-free B frags)
//  As  : 3*32*68 chunk ring (slot = gi%3); Cs aliases slot 2
//  cst : 512     cell state
//  bs  : 64      biases (gate*16+hc)
#define SMEM_FLOATS (64 * 772 + 3 * ASLOT + 512 + 64)

__global__ void __launch_bounds__(TB, 1)
lstm_persist(const float* __restrict__ x,
             const float* __restrict__ W_ix, const float* __restrict__ W_fx,
             const float* __restrict__ W_ox, const float* __restrict__ W_gx,
             const float* __restrict__ W_ih, const float* __restrict__ b_ih,
             const float* __restrict__ W_fh, const float* __restrict__ b_fh,
             const float* __restrict__ W_oh, const float* __restrict__ b_oh,
             const float* __restrict__ W_gh, const float* __restrict__ b_gh) {
    extern __shared__ float sm[];
    float* Ws = sm;
    float* As = Ws + 64 * 772;
    float* Cs = As + 2 * ASLOT; // alias of ring slot 2
    float* cst = As + 3 * ASLOT;
    float* bs = cst + 512;

    const int tid = threadIdx.x;
    const int cta = blockIdx.x;
    const int band = cta >> 5;
    const int col = cta & 31;
    const int hc0 = col * 16;
    const int brow0 = band * 32;

    const float* Whp[4] = {W_ih, W_fh, W_oh, W_gh};
    const float* Wxp[4] = {W_ix, W_fx, W_ox, W_gx};
    const float* bbp[4] = {b_ih, b_fh, b_oh, b_gh};

    // ---- Prologue: weight tile (tf32-rounded). n = gate*16+hc.
    // K order: [0,256) x weights, [256,768) h weights.
    for (int idx = tid; idx < 64 * 768; idx += TB) {
        int n = idx / 768;
        int k = idx - n * 768;
        int gate = n >> 4;
        int hc = hc0 + (n & 15);
        float v = (k < 256) ? Wxp[gate][hc * 256 + k] : Whp[gate][hc * 512 + (k - 256)];
        ((unsigned*)Ws)[n * 772 + k] = f2tf(v);
    }
    for (int i = tid; i < 64; i += TB) bs[i] = bbp[i >> 4][hc0 + (i & 15)];
    for (int i = tid; i < 512; i += TB) cst[i] = 0.f;
    __syncthreads();

    const int lane = tid & 31;
    const int w = tid >> 5;
    const int g = lane >> 2;
    const int tq = lane & 3;
    const int wr0 = (w & 1) * 16;
    const int wc0 = (w >> 1) * 16;

    // Chunk issue: gi = sti*12 + ci (sti = 0-based step). ci<4: x chunk (all
    // threads). ci>=4: h chunk -- warp 0 spins on the 4 producer flags (needs
    // h(sti), i.e. g_done >= sti), then warp 0 alone issues the loads. The
    // spin overlaps the other warps' mma of the current chunk.
    auto issue = [&](int gi) {
        if (gi >= TOTCHUNK) return;
        int sti = gi / NCHUNK;
        int ci = gi - sti * NCHUNK;
        float* buf = As + (gi % 3) * ASLOT;
        if (ci < 4) {
            const float* src = x + ((size_t)brow0 * 2048 + sti) * 256 + ci * 64;
            for (int it = tid; it < 512; it += TB) {
                int r = it >> 4, q = it & 15;
                cp16(buf + r * 68 + q * 4, src + (size_t)r * 2048 * 256 + q * 4);
            }
        } else if (w == 0) {
            int cbase = band * 32 + (ci - 4) * 4;
            bool ok;
            do {
                int v = (lane < 4) ? g_done[cbase + lane] : 0x7fffffff;
                ok = __all_sync(0xffffffffu, v >= sti);
            } while (!ok);
            asm volatile("fence.acq_rel.gpu;" ::: "memory");
            const float* hprev = g_h[sti & 1] + brow0 * 512 + (ci - 4) * 64;
            for (int it = lane; it < 512; it += 32) {
                int r = it >> 4, q = it & 15;
                cp16(buf + r * 68 + q * 4, hprev + r * 512 + q * 4);
            }
        }
    };

    // Ring prologue: chunks 0 and 1 (both x) in flight.
    issue(0); cp_commit();
    issue(1); cp_commit();

    for (int ti = 0; ti < 2048; ++ti) {
        float acc[2][4];
#pragma unroll
        for (int n = 0; n < 2; n++)
#pragma unroll
            for (int j = 0; j < 4; j++) acc[n][j] = 0.f;

        for (int kc = 0; kc < NCHUNK; ++kc) {
            int gi = ti * NCHUNK + kc;
            cp_wait1();      // chunk gi resident (pending: gi+1 only)
            __syncthreads(); // all warps past mma of gi-1 -> slot (gi+2)%3 free
            issue(gi + 2);
            cp_commit();

            const unsigned* Au = (const unsigned*)(As + (gi % 3) * ASLOT);
            const unsigned* Wu = (const unsigned*)Ws;
#pragma unroll
            for (int kk = 0; kk < 8; ++kk) {
                int kb = kk * 8 + tq;
                unsigned a0 = Au[(wr0 + g) * 68 + kb];
                unsigned a1 = Au[(wr0 + g + 8) * 68 + kb];
                unsigned a2 = Au[(wr0 + g) * 68 + kb + 4];
                unsigned a3 = Au[(wr0 + g + 8) * 68 + kb + 4];
#pragma unroll
                for (int nt = 0; nt < 2; ++nt) {
                    int wn = (wc0 + nt * 8 + g) * 772 + kc * 64 + kb;
                    mma_tf32(acc[nt], a0, a1, a2, a3, Wu[wn], Wu[wn + 4]);
                }
            }
        }

        __syncthreads(); // all mma of chunk 11 done -> slot 2 (Cs) reusable

        // ---- Gate preactivations to Cs
#pragma unroll
        for (int nt = 0; nt < 2; ++nt) {
            int c0 = wc0 + nt * 8 + 2 * tq;
            Cs[(wr0 + g) * 68 + c0] = acc[nt][0];
            Cs[(wr0 + g) * 68 + c0 + 1] = acc[nt][1];
            Cs[(wr0 + g + 8) * 68 + c0] = acc[nt][2];
            Cs[(wr0 + g + 8) * 68 + c0 + 1] = acc[nt][3];
        }
        __syncthreads();

        // ---- Cell update, h store (st.cg -> L2)
        float* hcur = g_h[(ti + 1) & 1];
        for (int it = tid; it < 512; it += TB) {
            int r = it >> 4, hc = it & 15;
            const float* Crow = Cs + r * 68;
            float zi = Crow[hc] + bs[hc];
            float zf = Crow[16 + hc] + bs[16 + hc];
            float zo = Crow[32 + hc] + bs[32 + hc];
            float zg = Crow[48 + hc] + bs[48 + hc];
            float gi_ = fsig(zi);
            float gf = fsig(zf);
            float go = fsig(zo);
            float gg = ftanh(zg);
            float c = gg * gi_ + cst[it] * gf;
            cst[it] = c;
            float h = ftanh(c) * go;
            stcg(&hcur[(brow0 + r) * 512 + hc0 + hc], h);
        }
        __threadfence();
        __syncthreads();
        if (tid == 0) g_done[cta] = ti + 1; // publish h(ti+1); also implies
                                            // "done reading h(ti)" -> WAR-safe
    }
}

__global__ void init_k() {
    int i = blockIdx.x * blockDim.x + threadIdx.x;
    if (i < 128) g_done[i] = 0;
    for (int j = i; j < 128 * 512; j += gridDim.x * blockDim.x) g_h[0][j] = 0.f;
}

// out[b][o] = sum_k h_final[b][k] * W_ph[o][k] + b_ph[o]   (h_final = g_h[0])
__global__ void __launch_bounds__(256) proj_k(const float* __restrict__ W_ph,
                                              const float* __restrict__ b_ph,
                                              float* __restrict__ out) {
    __shared__ float hs[512];
    int b = blockIdx.x;
    const float* hrow = g_h[0] + b * 512;
    for (int i = threadIdx.x; i < 512; i += 256) hs[i] = hrow[i];
    __syncthreads();
    int o = threadIdx.x;
    const float* wr = W_ph + o * 512;
    float acc = b_ph[o];
#pragma unroll 8
    for (int k = 0; k < 512; ++k) acc += hs[k] * wr[k];
    out[b * 256 + o] = acc;
}

extern "C" void kernel_launch(void* const* d_in, const int* in_sizes, int n_in,
                              void* d_out, int out_size) {
    (void)in_sizes; (void)n_in; (void)out_size;
    const float* x    = (const float*)d_in[0];
    const float* W_ix = (const float*)d_in[1];
    const float* W_fx = (const float*)d_in[2];
    const float* W_ox = (const float*)d_in[3];
    const float* W_gx = (const float*)d_in[4];
    const float* W_ih = (const float*)d_in[5];
    const float* b_ih = (const float*)d_in[6];
    const float* W_fh = (const float*)d_in[7];
    const float* b_fh = (const float*)d_in[8];
    const float* W_oh = (const float*)d_in[9];
    const float* b_oh = (const float*)d_in[10];
    const float* W_gh = (const float*)d_in[11];
    const float* b_gh = (const float*)d_in[12];
    const float* W_ph = (const float*)d_in[13];
    const float* b_ph = (const float*)d_in[14];

    size_t smem = (size_t)SMEM_FLOATS * sizeof(float); // 226048 B
    cudaFuncSetAttribute(lstm_persist, cudaFuncAttributeMaxDynamicSharedMemorySize, (int)smem);

    init_k<<<256, 256>>>();
    lstm_persist<<<128, TB, smem>>>(x, W_ix, W_fx, W_ox, W_gx,
                                    W_ih, b_ih, W_fh, b_fh, W_oh, b_oh, W_gh, b_gh);
    proj_k<<<128, 256>>>(W_ph, b_ph, (float*)d_out);
}

// round 7
// speedup vs baseline: 2.0293x; 2.0293x over previous
#include <cuda_runtime.h>
#include <cuda_fp16.h>
#include <cstdint>
#include <cstddef>

// B=128, S=2048, I=256, H=512, O=256
// Persistent fp16-operand LSTM (fp32 accumulate), R3-proven structure:
//  128 CTAs = 4 batch-bands(32 rows) x 32 column-CTAs(16 h-cols x 4 gates).
//  Weight tile [K=768][64 n] fp16 in SMEM, resident all 2048 steps (97 KB).
//  A=[x_t | h_{t-1}] fp16, 64-wide K chunks, 3-slot cp.async ring, depth-2
//  prefetch (wait_group 1). mma.sync.m16n8k16.f32.f16.f16.f32.
//  Monolithic per-band barrier + threadfence (proven R3 protocol).
//  x pre-converted to fp16 once per launch (static __device__ buffer).

#define TB 256
#define NCHUNK 12
#define TOT (2048 * NCHUNK)

// SMEM byte offsets
#define WSTR 388              // b32 per weight row (=776 halves), 388%32==4
#define ASTR 36               // b32 per A row (=72 halves)
#define ASLOT_B (32 * ASTR * 4) // 4608 bytes per slot
#define OFF_BS 0              // 64 floats bias
#define OFF_CST 256           // 512 floats cell state
#define OFF_CS 2304           // 32*68 floats gate preacts
#define OFF_W 11008           // 64*WSTR b32 = 99328 B
#define OFF_A 110336          // 3 slots
#define SMEM_BYTES (OFF_A + 3 * ASLOT_B) // 124160

static __device__ __half g_x16[128 * 2048 * 256]; // pre-converted x
static __device__ __half g_h16[2][128 * 512];
static __device__ int g_cnt[128];
static __device__ volatile int g_flag[128];

__device__ __forceinline__ void cp16(unsigned dst, const void* src) {
    asm volatile("cp.async.cg.shared.global [%0], [%1], 16;\n" ::"r"(dst), "l"(src));
}
__device__ __forceinline__ void cp_commit() { asm volatile("cp.async.commit_group;\n"); }
__device__ __forceinline__ void cp_wait1() { asm volatile("cp.async.wait_group 1;\n"); }

__device__ __forceinline__ void mma_f16(float c[4], unsigned a0, unsigned a1, unsigned a2,
                                        unsigned a3, unsigned b0, unsigned b1) {
    asm volatile(
        "mma.sync.aligned.m16n8k16.row.col.f32.f16.f16.f32 "
        "{%0,%1,%2,%3},{%4,%5,%6,%7},{%8,%9},{%0,%1,%2,%3};"
        : "+f"(c[0]), "+f"(c[1]), "+f"(c[2]), "+f"(c[3])
        : "r"(a0), "r"(a1), "r"(a2), "r"(a3), "r"(b0), "r"(b1));
}
__device__ __forceinline__ void sth(__half* p, __half v) {
    unsigned short u = __half_as_ushort(v);
    asm volatile("st.global.cg.u16 [%0], %1;" ::"l"(p), "h"(u));
}
__device__ __forceinline__ float fsig(float x) { return 1.f / (1.f + __expf(-x)); }
__device__ __forceinline__ float ftanh(float x) {
    float a = fabsf(x);
    float e = __expf(2.f * a);
    float r = 1.f - 2.f / (1.f + e);
    return copysignf(r, x);
}

__global__ void __launch_bounds__(TB, 1)
lstm_persist(const float* __restrict__ W_ix, const float* __restrict__ W_fx,
             const float* __restrict__ W_ox, const float* __restrict__ W_gx,
             const float* __restrict__ W_ih, const float* __restrict__ b_ih,
             const float* __restrict__ W_fh, const float* __restrict__ b_fh,
             const float* __restrict__ W_oh, const float* __restrict__ b_oh,
             const float* __restrict__ W_gh, const float* __restrict__ b_gh) {
    extern __shared__ __align__(16) char smem[];
    float* bs = (float*)(smem + OFF_BS);
    float* cst = (float*)(smem + OFF_CST);
    float* Cs = (float*)(smem + OFF_CS);
    __half* Wh = (__half*)(smem + OFF_W);
    const unsigned sb = (unsigned)__cvta_generic_to_shared(smem);

    const int tid = threadIdx.x;
    const int cta = blockIdx.x;
    const int band = cta >> 5;
    const int col = cta & 31;
    const int hc0 = col * 16;
    const int brow0 = band * 32;

    const float* Whp[4] = {W_ih, W_fh, W_oh, W_gh};
    const float* Wxp[4] = {W_ix, W_fx, W_ox, W_gx};
    const float* bbp[4] = {b_ih, b_fh, b_oh, b_gh};

    // ---- Prologue: weight tile fp16. n = gate*16+hc. K: [0,256) x, [256,768) h.
    for (int idx = tid; idx < 64 * 768; idx += TB) {
        int n = idx / 768;
        int k = idx - n * 768;
        int gate = n >> 4;
        int hc = hc0 + (n & 15);
        float v = (k < 256) ? Wxp[gate][hc * 256 + k] : Whp[gate][hc * 512 + (k - 256)];
        Wh[n * (WSTR * 2) + k] = __float2half_rn(v);
    }
    for (int i = tid; i < 64; i += TB) bs[i] = bbp[i >> 4][hc0 + (i & 15)];
    for (int i = tid; i < 512; i += TB) cst[i] = 0.f;
    __syncthreads();

    const int lane = tid & 31;
    const int w = tid >> 5;
    const int g = lane >> 2;
    const int tq = lane & 3;
    const int wr0 = (w & 1) * 16;  // warp row base
    const int wc0 = (w >> 1) * 16; // warp col base

    // Chunk issue: gi = sti*12 + ci. ci<4: x chunk; ci>=4: h chunk (h(sti),
    // guaranteed by the band barrier at the end of step sti-1 ... wait order
    // ensured because h chunks of step sti are only issued after that barrier).
    auto issue = [&](int gi) {
        if (gi >= TOT) return;
        int sti = gi / NCHUNK;
        int ci = gi - sti * NCHUNK;
        unsigned dst = sb + OFF_A + (unsigned)(gi % 3) * ASLOT_B;
        int r = tid >> 3, q = tid & 7; // 256 units: 32 rows x 8x16B
        unsigned d = dst + (unsigned)r * 144 + (unsigned)q * 16;
        if (ci < 4) {
            const __half* src = g_x16 + ((size_t)(brow0 + r) * 2048 + sti) * 256 + ci * 64 + q * 8;
            cp16(d, src);
        } else {
            const __half* src = g_h16[sti & 1] + (size_t)(brow0 + r) * 512 + (ci - 4) * 64 + q * 8;
            cp16(d, src);
        }
    };

    issue(0); cp_commit();
    issue(1); cp_commit();

    for (int ti = 0; ti < 2048; ++ti) {
        float acc[2][4];
#pragma unroll
        for (int n = 0; n < 2; n++)
#pragma unroll
            for (int j = 0; j < 4; j++) acc[n][j] = 0.f;

        for (int kc = 0; kc < NCHUNK; ++kc) {
            int gi = ti * NCHUNK + kc;
            cp_wait1();      // chunk gi resident (pending: gi+1)
            __syncthreads(); // everyone past mma of gi-1 -> slot (gi+2)%3 free
            issue(gi + 2);   // x chunks of next step prefetch across epilogue;
            cp_commit();     // h chunks of step ti issued at kc=2..9 (post-barrier)

            const unsigned* Au = (const unsigned*)(smem + OFF_A + (gi % 3) * ASLOT_B);
            const unsigned* Wu = (const unsigned*)(smem + OFF_W);
#pragma unroll
            for (int kk = 0; kk < 4; ++kk) { // 4 x K16
                int kb = kk * 8 + tq;        // b32 index within chunk (32 b32)
                unsigned a0 = Au[(wr0 + g) * ASTR + kb];
                unsigned a1 = Au[(wr0 + g + 8) * ASTR + kb];
                unsigned a2 = Au[(wr0 + g) * ASTR + kb + 4];
                unsigned a3 = Au[(wr0 + g + 8) * ASTR + kb + 4];
#pragma unroll
                for (int nt = 0; nt < 2; ++nt) {
                    int wn = (wc0 + nt * 8 + g) * WSTR + kc * 32 + kb;
                    mma_f16(acc[nt], a0, a1, a2, a3, Wu[wn], Wu[wn + 4]);
                }
            }
        }

        // ---- Gate preactivations to Cs
        __syncthreads();
#pragma unroll
        for (int nt = 0; nt < 2; ++nt) {
            int c0 = wc0 + nt * 8 + 2 * tq;
            Cs[(wr0 + g) * 68 + c0] = acc[nt][0];
            Cs[(wr0 + g) * 68 + c0 + 1] = acc[nt][1];
            Cs[(wr0 + g + 8) * 68 + c0] = acc[nt][2];
            Cs[(wr0 + g + 8) * 68 + c0 + 1] = acc[nt][3];
        }
        __syncthreads();

        // ---- Cell update (fp32), h store (fp16, st.cg -> L2)
        __half* hcur = g_h16[(ti + 1) & 1];
        for (int it = tid; it < 512; it += TB) {
            int r = it >> 4, hc = it & 15;
            const float* Crow = Cs + r * 68;
            float zi = Crow[hc] + bs[hc];
            float zf = Crow[16 + hc] + bs[16 + hc];
            float zo = Crow[32 + hc] + bs[32 + hc];
            float zg = Crow[48 + hc] + bs[48 + hc];
            float gi_ = fsig(zi);
            float gf = fsig(zf);
            float go = fsig(zo);
            float gg = ftanh(zg);
            float c = gg * gi_ + cst[it] * gf;
            cst[it] = c;
            float h = ftanh(c) * go;
            sth(&hcur[(size_t)(brow0 + r) * 512 + hc0 + hc], __float2half_rn(h));
        }
        __threadfence();
        __syncthreads();

        // ---- Monolithic per-band barrier (proven R3 protocol)
        if (tid == 0) {
            int prev = atomicAdd(&g_cnt[band * 32], 1);
            if (prev == 31) {
                atomicExch(&g_cnt[band * 32], 0);
                __threadfence();
                g_flag[band * 32] = ti + 1;
            } else {
                while (g_flag[band * 32] < ti + 1) { __nanosleep(64); }
                __threadfence();
            }
        }
        __syncthreads();
    }
}

__global__ void cvt_x(const float* __restrict__ x) {
    size_t n2 = (size_t)128 * 2048 * 256 / 2;
    size_t stride = (size_t)gridDim.x * blockDim.x;
    for (size_t i = (size_t)blockIdx.x * blockDim.x + threadIdx.x; i < n2; i += stride) {
        float2 v = ((const float2*)x)[i];
        ((__half2*)g_x16)[i] = __floats2half2_rn(v.x, v.y);
    }
}

__global__ void init_k() {
    int i = blockIdx.x * blockDim.x + threadIdx.x;
    if (i < 128) {
        g_cnt[i] = 0;
        g_flag[i] = 0;
    }
    for (int j = i; j < 128 * 512 / 2; j += gridDim.x * blockDim.x)
        ((__half2*)g_h16[0])[j] = __floats2half2_rn(0.f, 0.f);
}

// out[b][o] = h_final[b] . W_ph[o] + b_ph[o]; h_final = g_h16[0] (2048 even)
__global__ void __launch_bounds__(256) proj_k(const float* __restrict__ W_ph,
                                              const float* __restrict__ b_ph,
                                              float* __restrict__ out) {
    __shared__ float hs[512];
    int b = blockIdx.x;
    const __half* hrow = g_h16[0] + (size_t)b * 512;
    for (int i = threadIdx.x; i < 512; i += 256) hs[i] = __half2float(hrow[i]);
    __syncthreads();
    int o = threadIdx.x;
    const float* wr = W_ph + o * 512;
    float acc = b_ph[o];
#pragma unroll 8
    for (int k = 0; k < 512; ++k) acc += hs[k] * wr[k];
    out[b * 256 + o] = acc;
}

extern "C" void kernel_launch(void* const* d_in, const int* in_sizes, int n_in,
                              void* d_out, int out_size) {
    (void)in_sizes; (void)n_in; (void)out_size;
    const float* x    = (const float*)d_in[0];
    const float* W_ix = (const float*)d_in[1];
    const float* W_fx = (const float*)d_in[2];
    const float* W_ox = (const float*)d_in[3];
    const float* W_gx = (const float*)d_in[4];
    const float* W_ih = (const float*)d_in[5];
    const float* b_ih = (const float*)d_in[6];
    const float* W_fh = (const float*)d_in[7];
    const float* b_fh = (const float*)d_in[8];
    const float* W_oh = (const float*)d_in[9];
    const float* b_oh = (const float*)d_in[10];
    const float* W_gh = (const float*)d_in[11];
    const float* b_gh = (const float*)d_in[12];
    const float* W_ph = (const float*)d_in[13];
    const float* b_ph = (const float*)d_in[14];

    cudaFuncSetAttribute(lstm_persist, cudaFuncAttributeMaxDynamicSharedMemorySize, SMEM_BYTES);

    cvt_x<<<2048, 256>>>(x);
    init_k<<<256, 256>>>();
    lstm_persist<<<128, TB, SMEM_BYTES>>>(W_ix, W_fx, W_ox, W_gx,
                                          W_ih, b_ih, W_fh, b_fh, W_oh, b_oh, W_gh, b_gh);
    proj_k<<<128, 256>>>(W_ph, b_ph, (float*)d_out);
}

// round 8
// speedup vs baseline: 3.1019x; 1.5285x over previous
#include <cuda_runtime.h>
#include <cuda_fp16.h>
#include <cstdint>
#include <cstddef>

// B=128, S=2048, I=256, H=512, O=256
// Persistent fp16 LSTM, weights-in-registers:
//  128 CTAs = 4 batch-bands(32 rows) x 32 column-CTAs(16 h-cols x 4 gates).
//  B fragments (192 b32/thread, fp16x2) hoisted to registers ONCE; mma.sync
//  m16n8k16 f32.f16.f16.f32 reads B from regs -> zero weight LDS in mainloop.
//  A=[x|h] fp16, 128-wide K chunks (6/step), 3-slot cp.async ring, depth-2
//  prefetch (wait_group 1); slot = kc%3 compile-time.
//  kc 0..3 issue h chunks (this step), kc 4..5 prefetch next step's x chunks.
//  Monolithic per-band barrier (proven), single-fence release in epilogue.

#define TB 256
#define ASTR 68                   // b32 per A row (136 halves)
#define ASLOT_B (32 * ASTR * 4)   // 8704 B per ring slot
#define OFF_BS 0                  // 64 floats bias
#define OFF_CST 256               // 512 floats cell state
#define OFF_CS 2304               // 32*68 floats gate preacts (8704 B)
#define OFF_A 11008               // ring: 3 slots (staging aliases this at init)
#define SMEM_BYTES (OFF_A + 3 * ASLOT_B) // 37120

static __device__ __half g_x16[128 * 2048 * 256];
static __device__ __half g_h16[2][128 * 512];
static __device__ int g_cnt[128];
static __device__ volatile int g_flag[128];

__device__ __forceinline__ void cp16(unsigned dst, const void* src) {
    asm volatile("cp.async.cg.shared.global [%0], [%1], 16;\n" ::"r"(dst), "l"(src));
}
__device__ __forceinline__ void cp_commit() { asm volatile("cp.async.commit_group;\n"); }
__device__ __forceinline__ void cp_wait1() { asm volatile("cp.async.wait_group 1;\n"); }

__device__ __forceinline__ void mma_f16(float c[4], unsigned a0, unsigned a1, unsigned a2,
                                        unsigned a3, unsigned b0, unsigned b1) {
    asm volatile(
        "mma.sync.aligned.m16n8k16.row.col.f32.f16.f16.f32 "
        "{%0,%1,%2,%3},{%4,%5,%6,%7},{%8,%9},{%0,%1,%2,%3};"
        : "+f"(c[0]), "+f"(c[1]), "+f"(c[2]), "+f"(c[3])
        : "r"(a0), "r"(a1), "r"(a2), "r"(a3), "r"(b0), "r"(b1));
}
__device__ __forceinline__ void sth(__half* p, __half v) {
    unsigned short u = __half_as_ushort(v);
    asm volatile("st.global.cg.u16 [%0], %1;" ::"l"(p), "h"(u));
}
__device__ __forceinline__ float fsig(float x) { return 1.f / (1.f + __expf(-x)); }
__device__ __forceinline__ float ftanh(float x) {
    float a = fabsf(x);
    float e = __expf(2.f * a);
    float r = 1.f - 2.f / (1.f + e);
    return copysignf(r, x);
}

__global__ void __launch_bounds__(TB, 1)
lstm_persist(const float* __restrict__ W_ix, const float* __restrict__ W_fx,
             const float* __restrict__ W_ox, const float* __restrict__ W_gx,
             const float* __restrict__ W_ih, const float* __restrict__ b_ih,
             const float* __restrict__ W_fh, const float* __restrict__ b_fh,
             const float* __restrict__ W_oh, const float* __restrict__ b_oh,
             const float* __restrict__ W_gh, const float* __restrict__ b_gh) {
    extern __shared__ __align__(16) char smem[];
    float* bs = (float*)(smem + OFF_BS);
    float* cst = (float*)(smem + OFF_CST);
    float* Cs = (float*)(smem + OFF_CS);
    const unsigned sb = (unsigned)__cvta_generic_to_shared(smem);

    const int tid = threadIdx.x;
    const int cta = blockIdx.x;
    const int band = cta >> 5;
    const int col = cta & 31;
    const int hc0 = col * 16;
    const int brow0 = band * 32;

    const int lane = tid & 31;
    const int w = tid >> 5;
    const int g = lane >> 2;
    const int tq = lane & 3;
    const int wr0 = (w & 1) * 16;  // warp row base (0/16)
    const int wc0 = (w >> 1) * 16; // warp col base (0/16/32/48)

    const float* Whp[4] = {W_ih, W_fh, W_oh, W_gh};
    const float* Wxp[4] = {W_ix, W_fx, W_ox, W_gx};
    const float* bbp[4] = {b_ih, b_fh, b_oh, b_gh};

    for (int i = tid; i < 64; i += TB) bs[i] = bbp[i >> 4][hc0 + (i & 15)];
    for (int i = tid; i < 512; i += TB) cst[i] = 0.f;

    // ---- Hoist B fragments into registers, one 128-K chunk at a time,
    // staging through the A-ring smem area (17408 B <= 26112 B).
    unsigned Breg[6][8][2][2];
    {
        __half* Wt = (__half*)(smem + OFF_A);
        const unsigned* Wu = (const unsigned*)(smem + OFF_A);
#pragma unroll
        for (int kc = 0; kc < 6; ++kc) {
            __syncthreads();
            for (int idx = tid; idx < 64 * 128; idx += TB) {
                int n = idx >> 7;
                int kl = idx & 127;
                int k = kc * 128 + kl;
                int gate = n >> 4;
                int hc = hc0 + (n & 15);
                float v = (k < 256) ? Wxp[gate][hc * 256 + k]
                                    : Whp[gate][hc * 512 + (k - 256)];
                Wt[n * 136 + kl] = __float2half_rn(v);
            }
            __syncthreads();
#pragma unroll
            for (int kk = 0; kk < 8; ++kk)
#pragma unroll
                for (int nt = 0; nt < 2; ++nt) {
                    int wn = (wc0 + nt * 8 + g) * ASTR + kk * 8 + tq;
                    Breg[kc][kk][nt][0] = Wu[wn];
                    Breg[kc][kk][nt][1] = Wu[wn + 4];
                }
        }
        __syncthreads();
    }

    // ---- Per-thread A-chunk staging addresses (2 x cp16 per thread per chunk)
    const int ar = tid >> 3;      // 0..31 row
    const int aq = tid & 7;       // 0..7
    const unsigned dA0 = (unsigned)ar * 272 + (unsigned)aq * 16;
    // x: [(brow0+ar)*2048 + sti]*256 + ci*128 + {aq*8, aq*8+64}
    const size_t xrow = ((size_t)(brow0 + ar) * 2048) * 256;
    const size_t hrow = (size_t)(brow0 + ar) * 512;

    auto issue_x = [&](int sti, int ci, int slot) {
        if (sti >= 2048) return;
        unsigned d = sb + OFF_A + (unsigned)slot * ASLOT_B + dA0;
        const __half* s = g_x16 + xrow + (size_t)sti * 256 + ci * 128 + aq * 8;
        cp16(d, s);
        cp16(d + 128, s + 64);
    };
    auto issue_h = [&](int sti, int ci, int slot) {
        unsigned d = sb + OFF_A + (unsigned)slot * ASLOT_B + dA0;
        const __half* s = g_h16[sti & 1] + hrow + (ci - 2) * 128 + aq * 8;
        cp16(d, s);
        cp16(d + 128, s + 64);
    };

    // Prime ring: chunks 0,1 of step 0 (both x).
    issue_x(0, 0, 0); cp_commit();
    issue_x(0, 1, 1); cp_commit();

    for (int ti = 0; ti < 2048; ++ti) {
        float acc[2][4];
#pragma unroll
        for (int n = 0; n < 2; n++)
#pragma unroll
            for (int j = 0; j < 4; j++) acc[n][j] = 0.f;

#pragma unroll
        for (int kc = 0; kc < 6; ++kc) {
            cp_wait1();      // chunk kc resident (pending: kc+1)
            __syncthreads(); // all warps done with mma of kc-1 -> slot free
            if (kc < 4) issue_h(ti, kc + 2, (kc + 2) % 3);
            else        issue_x(ti + 1, kc - 4, (kc + 2) % 3);
            cp_commit();

            const unsigned* Au = (const unsigned*)(smem + OFF_A + (kc % 3) * ASLOT_B);
#pragma unroll
            for (int kk = 0; kk < 8; ++kk) {
                int kb = kk * 8 + tq;
                unsigned a0 = Au[(wr0 + g) * ASTR + kb];
                unsigned a1 = Au[(wr0 + g + 8) * ASTR + kb];
                unsigned a2 = Au[(wr0 + g) * ASTR + kb + 4];
                unsigned a3 = Au[(wr0 + g + 8) * ASTR + kb + 4];
                mma_f16(acc[0], a0, a1, a2, a3, Breg[kc][kk][0][0], Breg[kc][kk][0][1]);
                mma_f16(acc[1], a0, a1, a2, a3, Breg[kc][kk][1][0], Breg[kc][kk][1][1]);
            }
        }

        // ---- Gate preactivations to Cs
        __syncthreads();
#pragma unroll
        for (int nt = 0; nt < 2; ++nt) {
            int c0 = wc0 + nt * 8 + 2 * tq;
            Cs[(wr0 + g) * 68 + c0] = acc[nt][0];
            Cs[(wr0 + g) * 68 + c0 + 1] = acc[nt][1];
            Cs[(wr0 + g + 8) * 68 + c0] = acc[nt][2];
            Cs[(wr0 + g + 8) * 68 + c0 + 1] = acc[nt][3];
        }
        __syncthreads();

        // ---- Cell update (fp32), h store (fp16, st.cg -> L2)
        __half* hcur = g_h16[(ti + 1) & 1];
        for (int it = tid; it < 512; it += TB) {
            int r = it >> 4, hc = it & 15;
            const float* Crow = Cs + r * 68;
            float zi = Crow[hc] + bs[hc];
            float zf = Crow[16 + hc] + bs[16 + hc];
            float zo = Crow[32 + hc] + bs[32 + hc];
            float zg = Crow[48 + hc] + bs[48 + hc];
            float gi_ = fsig(zi);
            float gf = fsig(zf);
            float go = fsig(zo);
            float gg = ftanh(zg);
            float c = gg * gi_ + cst[it] * gf;
            cst[it] = c;
            float h = ftanh(c) * go;
            sth(&hcur[(size_t)(brow0 + r) * 512 + hc0 + hc], __float2half_rn(h));
        }
        __syncthreads(); // all h stores issued (program order) before release

        // ---- Monolithic per-band barrier, single-fence release (tid 0)
        if (tid == 0) {
            asm volatile("fence.acq_rel.gpu;" ::: "memory");
            int prev = atomicAdd(&g_cnt[band * 32], 1);
            if (prev == 31) {
                atomicExch(&g_cnt[band * 32], 0);
                g_flag[band * 32] = ti + 1;
            } else {
                while (g_flag[band * 32] < ti + 1) { __nanosleep(64); }
                asm volatile("fence.acq_rel.gpu;" ::: "memory");
            }
        }
        __syncthreads();
    }
}

__global__ void cvt_x(const float* __restrict__ x) {
    size_t n2 = (size_t)128 * 2048 * 256 / 2;
    size_t stride = (size_t)gridDim.x * blockDim.x;
    for (size_t i = (size_t)blockIdx.x * blockDim.x + threadIdx.x; i < n2; i += stride) {
        float2 v = ((const float2*)x)[i];
        ((__half2*)g_x16)[i] = __floats2half2_rn(v.x, v.y);
    }
}

__global__ void init_k() {
    int i = blockIdx.x * blockDim.x + threadIdx.x;
    if (i < 128) {
        g_cnt[i] = 0;
        g_flag[i] = 0;
    }
    for (int j = i; j < 128 * 512 / 2; j += gridDim.x * blockDim.x)
        ((__half2*)g_h16[0])[j] = __floats2half2_rn(0.f, 0.f);
}

// out[b][o] = h_final[b] . W_ph[o] + b_ph[o]; h_final = g_h16[0] (2048 even)
__global__ void __launch_bounds__(256) proj_k(const float* __restrict__ W_ph,
                                              const float* __restrict__ b_ph,
                                              float* __restrict__ out) {
    __shared__ float hs[512];
    int b = blockIdx.x;
    const __half* hrow = g_h16[0] + (size_t)b * 512;
    for (int i = threadIdx.x; i < 512; i += 256) hs[i] = __half2float(hrow[i]);
    __syncthreads();
    int o = threadIdx.x;
    const float* wr = W_ph + o * 512;
    float acc = b_ph[o];
#pragma unroll 8
    for (int k = 0; k < 512; ++k) acc += hs[k] * wr[k];
    out[b * 256 + o] = acc;
}

extern "C" void kernel_launch(void* const* d_in, const int* in_sizes, int n_in,
                              void* d_out, int out_size) {
    (void)in_sizes; (void)n_in; (void)out_size;
    const float* x    = (const float*)d_in[0];
    const float* W_ix = (const float*)d_in[1];
    const float* W_fx = (const float*)d_in[2];
    const float* W_ox = (const float*)d_in[3];
    const float* W_gx = (const float*)d_in[4];
    const float* W_ih = (const float*)d_in[5];
    const float* b_ih = (const float*)d_in[6];
    const float* W_fh = (const float*)d_in[7];
    const float* b_fh = (const float*)d_in[8];
    const float* W_oh = (const float*)d_in[9];
    const float* b_oh = (const float*)d_in[10];
    const float* W_gh = (const float*)d_in[11];
    const float* b_gh = (const float*)d_in[12];
    const float* W_ph = (const float*)d_in[13];
    const float* b_ph = (const float*)d_in[14];

    cudaFuncSetAttribute(lstm_persist, cudaFuncAttributeMaxDynamicSharedMemorySize, SMEM_BYTES);

    cvt_x<<<2048, 256>>>(x);
    init_k<<<256, 256>>>();
    lstm_persist<<<128, TB, SMEM_BYTES>>>(W_ix, W_fx, W_ox, W_gx,
                                          W_ih, b_ih, W_fh, b_fh, W_oh, b_oh, W_gh, b_gh);
    proj_k<<<128, 256>>>(W_ph, b_ph, (float*)d_out);
}